// round 2
// baseline (speedup 1.0000x reference)
#include <cuda_runtime.h>
#include <math_constants.h>

#define BB   8
#define CIN  512
#define NN   4096
#define DDIM 256
#define KKE  2048

// packed fp32x2 FMA (Blackwell): d = a*b + c elementwise on 2 packed floats
#define FMA_F32X2(d, a, b, c) \
    asm("fma.rn.f32x2 %0, %1, %2, %3;" : "=l"(d) : "l"(a), "l"(b), "l"(c))
#define UNPACK2(lo, hi, in) \
    asm("mov.b64 {%0, %1}, %2;" : "=f"(lo), "=f"(hi) : "l"(in))

// ---- scratch (device globals; no allocation allowed) ----
__device__ float g_ze[BB * DDIM * NN];     // (B, D, N) conv output
__device__ float g_esq[KKE];               // ||e_k||^2
__device__ int   g_minidx[BB * NN];        // argmin indices
__device__ float g_zsum[KKE * DDIM];       // segment sums
__device__ float g_nsum[KKE];              // segment counts

// ============================================================
// e_sq: one warp per codebook row
// ============================================================
__global__ void esq_kernel(const float* __restrict__ emb) {
    int warp = (blockIdx.x * blockDim.x + threadIdx.x) >> 5;
    int lane = threadIdx.x & 31;
    if (warp >= KKE) return;
    const float* row = emb + (size_t)warp * DDIM;
    float s = 0.f;
#pragma unroll
    for (int i = lane; i < DDIM; i += 32) { float v = row[i]; s += v * v; }
#pragma unroll
    for (int off = 16; off; off >>= 1) s += __shfl_down_sync(0xffffffffu, s, off);
    if (lane == 0) g_esq[warp] = s;
}

// ============================================================
// GEMM1: ze[b,d,n] = sum_c W[d,c] * z[b,c,n]
// block tile: 64 (d) x 128 (n), K-chunk 16 over CIN
// f32x2 packed FMA; W tile stored duplicated (w,w) pairs.
// ============================================================
__global__ void __launch_bounds__(256, 2) gemm1_kernel(
    const float* __restrict__ z, const float* __restrict__ W)
{
    __shared__ float Ws2[16][136];   // [c][2*d_local] duplicated pairs, padded
    __shared__ float Zs[16][128];    // [c][n_local]

    const int n0 = blockIdx.x * 128;
    const int d0 = blockIdx.y * 64;
    const int b  = blockIdx.z;
    const int tid = threadIdx.x;
    const int tk = tid >> 4;
    const int tn = tid & 15;

    unsigned long long acc2[4][4];   // [d][n-pair]
#pragma unroll
    for (int i = 0; i < 4; i++)
#pragma unroll
        for (int j = 0; j < 4; j++) acc2[i][j] = 0ull;

    for (int c0 = 0; c0 < CIN; c0 += 16) {
#pragma unroll
        for (int i = 0; i < 4; i++) {          // 64x16 W tile -> duplicated
            int lin = tid + 256 * i;
            int dl = lin >> 4, cc = lin & 15;
            float v = W[(size_t)(d0 + dl) * CIN + c0 + cc];
            Ws2[cc][2 * dl]     = v;
            Ws2[cc][2 * dl + 1] = v;
        }
#pragma unroll
        for (int i = 0; i < 8; i++) {          // 16x128 z tile
            int lin = tid + 256 * i;
            int cc = lin >> 7, nl = lin & 127;
            Zs[cc][nl] = z[((size_t)b * CIN + c0 + cc) * NN + n0 + nl];
        }
        __syncthreads();
#pragma unroll
        for (int cc = 0; cc < 16; cc++) {
            ulonglong2 a01 = *(const ulonglong2*)&Ws2[cc][tk * 8];
            ulonglong2 a23 = *(const ulonglong2*)&Ws2[cc][tk * 8 + 4];
            ulonglong2 b01 = *(const ulonglong2*)&Zs[cc][tn * 8];
            ulonglong2 b23 = *(const ulonglong2*)&Zs[cc][tn * 8 + 4];
            unsigned long long av[4] = {a01.x, a01.y, a23.x, a23.y};
            unsigned long long bv[4] = {b01.x, b01.y, b23.x, b23.y};
#pragma unroll
            for (int i = 0; i < 4; i++)
#pragma unroll
                for (int j = 0; j < 4; j++)
                    FMA_F32X2(acc2[i][j], av[i], bv[j], acc2[i][j]);
        }
        __syncthreads();
    }
#pragma unroll
    for (int i = 0; i < 4; i++) {
        int d = d0 + tk * 4 + i;
        float* dst = &g_ze[((size_t)b * DDIM + d) * NN + n0 + tn * 8];
        ulonglong2 s0; s0.x = acc2[i][0]; s0.y = acc2[i][1];
        ulonglong2 s1; s1.x = acc2[i][2]; s1.y = acc2[i][3];
        *(ulonglong2*)dst       = s0;
        *(ulonglong2*)(dst + 4) = s1;
    }
}

// ============================================================
// GEMM2 + fused argmin:
//   score[k,n] = e_sq[k] - 2 * sum_d e[k,d]*ze[b,d,n]
//   min over k per (b,n) -> g_minidx
// f32x2 packed FMA; E tile stored duplicated (e,e) pairs.
// ============================================================
__global__ void __launch_bounds__(256, 2) argmin_kernel(const float* __restrict__ emb)
{
    __shared__ float Es2[16][136];   // [d][2*k_local] duplicated pairs, padded
    __shared__ float Zs[16][128];    // [d][n_local]
    __shared__ float rv[16][128];
    __shared__ int   ri[16][128];

    const int n0 = blockIdx.x * 128;
    const int b  = blockIdx.y;
    const int tid = threadIdx.x;
    const int tk = tid >> 4;
    const int tn = tid & 15;

    float vmin[8];
    int   imin[8];
#pragma unroll
    for (int j = 0; j < 8; j++) { vmin[j] = CUDART_INF_F; imin[j] = 0; }

    for (int k0 = 0; k0 < KKE; k0 += 64) {
        unsigned long long acc2[4][4];   // [k][n-pair]
#pragma unroll
        for (int i = 0; i < 4; i++)
#pragma unroll
            for (int j = 0; j < 4; j++) acc2[i][j] = 0ull;

        for (int d0 = 0; d0 < DDIM; d0 += 16) {
#pragma unroll
            for (int i = 0; i < 4; i++) {      // 64x16 E tile (transposed) -> duplicated
                int lin = tid + 256 * i;
                int kl = lin >> 4, dd = lin & 15;
                float v = emb[(size_t)(k0 + kl) * DDIM + d0 + dd];
                Es2[dd][2 * kl]     = v;
                Es2[dd][2 * kl + 1] = v;
            }
#pragma unroll
            for (int i = 0; i < 8; i++) {      // 16x128 ze tile
                int lin = tid + 256 * i;
                int dd = lin >> 7, nl = lin & 127;
                Zs[dd][nl] = g_ze[((size_t)b * DDIM + d0 + dd) * NN + n0 + nl];
            }
            __syncthreads();
#pragma unroll
            for (int dc = 0; dc < 16; dc++) {
                ulonglong2 a01 = *(const ulonglong2*)&Es2[dc][tk * 8];
                ulonglong2 a23 = *(const ulonglong2*)&Es2[dc][tk * 8 + 4];
                ulonglong2 b01 = *(const ulonglong2*)&Zs[dc][tn * 8];
                ulonglong2 b23 = *(const ulonglong2*)&Zs[dc][tn * 8 + 4];
                unsigned long long av[4] = {a01.x, a01.y, a23.x, a23.y};
                unsigned long long bv[4] = {b01.x, b01.y, b23.x, b23.y};
#pragma unroll
                for (int i = 0; i < 4; i++)
#pragma unroll
                    for (int j = 0; j < 4; j++)
                        FMA_F32X2(acc2[i][j], av[i], bv[j], acc2[i][j]);
            }
            __syncthreads();
        }
        // fused argmin update (k ascending => strict '<' keeps lowest index)
#pragma unroll
        for (int i = 0; i < 4; i++) {
            int k = k0 + tk * 4 + i;
            float eq = g_esq[k];
#pragma unroll
            for (int j = 0; j < 4; j++) {
                float lo, hi;
                UNPACK2(lo, hi, acc2[i][j]);
                float s0 = eq - 2.f * lo;
                float s1 = eq - 2.f * hi;
                if (s0 < vmin[2 * j])     { vmin[2 * j]     = s0; imin[2 * j]     = k; }
                if (s1 < vmin[2 * j + 1]) { vmin[2 * j + 1] = s1; imin[2 * j + 1] = k; }
            }
        }
    }
    // cross-thread reduction over the 16 tk-slices per column
#pragma unroll
    for (int j = 0; j < 8; j++) {
        rv[tk][tn * 8 + j] = vmin[j];
        ri[tk][tn * 8 + j] = imin[j];
    }
    __syncthreads();
    if (tid < 128) {
        int n = tid;
        float bv2 = rv[0][n];
        int bi = ri[0][n];
#pragma unroll
        for (int t = 1; t < 16; t++) {
            float v = rv[t][n];
            int i2 = ri[t][n];
            if (v < bv2 || (v == bv2 && i2 < bi)) { bv2 = v; bi = i2; }
        }
        g_minidx[(size_t)b * NN + n0 + n] = bi;
    }
}

// ============================================================
// zero scatter buffers (must re-zero every launch: graph replay)
// ============================================================
__global__ void zero_kernel() {
    int total = KKE * DDIM + KKE;
    for (int i = blockIdx.x * blockDim.x + threadIdx.x; i < total;
         i += gridDim.x * blockDim.x) {
        if (i < KKE * DDIM) g_zsum[i] = 0.f;
        else g_nsum[i - KKE * DDIM] = 0.f;
    }
}

// ============================================================
// gather zq -> out, scatter-add ze into z_sum / n_sum
// ============================================================
__global__ void gs_kernel(const float* __restrict__ emb, float* __restrict__ out)
{
    const int b = blockIdx.y;
    const int n = blockIdx.x * 32 + threadIdx.x;
    const int ty = threadIdx.y;
    const int idx = g_minidx[(size_t)b * NN + n];
#pragma unroll 4
    for (int d = ty; d < DDIM; d += 8) {
        size_t zoff = ((size_t)b * DDIM + d) * NN + n;
        float zev = g_ze[zoff];
        out[zoff] = emb[(size_t)idx * DDIM + d];   // straight-through value == zq
        atomicAdd(&g_zsum[(size_t)idx * DDIM + d], zev);
    }
    if (ty == 0) atomicAdd(&g_nsum[idx], 1.0f);
}

// ============================================================
// EMA finalize -> tail of d_out
// ============================================================
__global__ void ema_kernel(const float* __restrict__ ema_numer,
                           const float* __restrict__ ema_denom,
                           float* __restrict__ out)
{
    const size_t OUT_OFF = (size_t)BB * DDIM * NN;
    int i = blockIdx.x * blockDim.x + threadIdx.x;
    if (i < KKE * DDIM)
        out[OUT_OFF + i] = 0.99f * ema_numer[i] + 0.01f * g_zsum[i];
    if (i < KKE)
        out[OUT_OFF + (size_t)KKE * DDIM + i] = 0.99f * ema_denom[i] + 0.01f * g_nsum[i];
}

// ============================================================
extern "C" void kernel_launch(void* const* d_in, const int* in_sizes, int n_in,
                              void* d_out, int out_size)
{
    const float* z         = (const float*)d_in[0];
    const float* W         = (const float*)d_in[1];
    const float* emb       = (const float*)d_in[2];
    const float* ema_numer = (const float*)d_in[3];
    const float* ema_denom = (const float*)d_in[4];
    float* out = (float*)d_out;
    (void)in_sizes; (void)n_in; (void)out_size;

    // 1. codebook squared norms
    esq_kernel<<<(KKE * 32 + 255) / 256, 256>>>(emb);

    // 2. ze = W * z  (1x1 conv)
    {
        dim3 grid(NN / 128, DDIM / 64, BB);
        gemm1_kernel<<<grid, 256>>>(z, W);
    }

    // 3. fused distance GEMM + argmin
    {
        dim3 grid(NN / 128, BB);
        argmin_kernel<<<grid, 256>>>(emb);
    }

    // 4. zero scatter buffers
    zero_kernel<<<512, 256>>>();

    // 5. gather zq + scatter EMA statistics
    {
        dim3 grid(NN / 32, BB);
        dim3 blk(32, 8);
        gs_kernel<<<grid, blk>>>(emb, out);
    }

    // 6. EMA blend
    ema_kernel<<<(KKE * DDIM + 255) / 256, 256>>>(ema_numer, ema_denom, out);
}

// round 3
// speedup vs baseline: 1.6109x; 1.6109x over previous
#include <cuda_runtime.h>
#include <math_constants.h>

#define BB   8
#define CIN  512
#define NN   4096
#define DDIM 256
#define KKE  2048

// ---- scratch (device globals; no allocation allowed) ----
__device__ float g_ze[BB * DDIM * NN];     // (B, D, N) conv output
__device__ float g_esq[KKE];               // ||e_k||^2
__device__ int   g_minidx[BB * NN];        // argmin indices
__device__ float g_zsum[KKE * DDIM];       // segment sums
__device__ float g_nsum[KKE];              // segment counts

// ============================================================
// e_sq: one warp per codebook row
// ============================================================
__global__ void esq_kernel(const float* __restrict__ emb) {
    int warp = (blockIdx.x * blockDim.x + threadIdx.x) >> 5;
    int lane = threadIdx.x & 31;
    if (warp >= KKE) return;
    const float* row = emb + (size_t)warp * DDIM;
    float s = 0.f;
#pragma unroll
    for (int i = lane; i < DDIM; i += 32) { float v = row[i]; s += v * v; }
#pragma unroll
    for (int off = 16; off; off >>= 1) s += __shfl_down_sync(0xffffffffu, s, off);
    if (lane == 0) g_esq[warp] = s;
}

// ============================================================
// GEMM1: ze[b,d,n] = sum_c W[d,c] * z[b,c,n]
// block tile: 64 (d) x 128 (n), K-chunk 16 over CIN (R1 version)
// ============================================================
__global__ void __launch_bounds__(256, 2) gemm1_kernel(
    const float* __restrict__ z, const float* __restrict__ W)
{
    __shared__ float Ws[16][68];    // [c][d_local], padded
    __shared__ float Zs[16][128];   // [c][n_local]

    const int n0 = blockIdx.x * 128;
    const int d0 = blockIdx.y * 64;
    const int b  = blockIdx.z;
    const int tid = threadIdx.x;
    const int tk = tid >> 4;
    const int tn = tid & 15;

    float acc[4][8];
#pragma unroll
    for (int i = 0; i < 4; i++)
#pragma unroll
        for (int j = 0; j < 8; j++) acc[i][j] = 0.f;

    for (int c0 = 0; c0 < CIN; c0 += 16) {
#pragma unroll
        for (int i = 0; i < 4; i++) {          // 64x16 W tile
            int lin = tid + 256 * i;
            int dl = lin >> 4, cc = lin & 15;
            Ws[cc][dl] = W[(size_t)(d0 + dl) * CIN + c0 + cc];
        }
#pragma unroll
        for (int i = 0; i < 8; i++) {          // 16x128 z tile
            int lin = tid + 256 * i;
            int cc = lin >> 7, nl = lin & 127;
            Zs[cc][nl] = z[((size_t)b * CIN + c0 + cc) * NN + n0 + nl];
        }
        __syncthreads();
#pragma unroll
        for (int cc = 0; cc < 16; cc++) {
            float4 av = *(const float4*)&Ws[cc][tk * 4];
            float4 b0 = *(const float4*)&Zs[cc][tn * 8];
            float4 b1 = *(const float4*)&Zs[cc][tn * 8 + 4];
            float a[4] = {av.x, av.y, av.z, av.w};
            float bv[8] = {b0.x, b0.y, b0.z, b0.w, b1.x, b1.y, b1.z, b1.w};
#pragma unroll
            for (int i = 0; i < 4; i++)
#pragma unroll
                for (int j = 0; j < 8; j++) acc[i][j] += a[i] * bv[j];
        }
        __syncthreads();
    }
#pragma unroll
    for (int i = 0; i < 4; i++) {
        int d = d0 + tk * 4 + i;
        float* dst = &g_ze[((size_t)b * DDIM + d) * NN + n0 + tn * 8];
        *(float4*)dst       = make_float4(acc[i][0], acc[i][1], acc[i][2], acc[i][3]);
        *(float4*)(dst + 4) = make_float4(acc[i][4], acc[i][5], acc[i][6], acc[i][7]);
    }
}

// ============================================================
// GEMM2 + fused argmin (v2: 8x8 register blocking):
//   score[k,n] = e_sq[k] - 2 * sum_d e[k,d]*ze[b,d,n]
// block: b, 128 n-cols. k-tiles of 128, d-chunks of 32.
// 256 threads = 16(tk) x 16(tn), each 8k x 8n.
// ============================================================
__global__ void __launch_bounds__(256, 2) argmin_kernel(const float* __restrict__ emb)
{
    __shared__ float Es[32][132];    // [d][k_local], padded (stride 132 mod 32 = 4)
    __shared__ float Zs[32][132];    // [d][n_local]
    __shared__ float esq_s[128];

    const int n0 = blockIdx.x * 128;
    const int b  = blockIdx.y;
    const int tid = threadIdx.x;
    const int tk = tid >> 4;
    const int tn = tid & 15;

    float vmin[8];
    int   imin[8];
#pragma unroll
    for (int j = 0; j < 8; j++) { vmin[j] = CUDART_INF_F; imin[j] = 0; }

    for (int k0 = 0; k0 < KKE; k0 += 128) {
        float acc[8][8];
#pragma unroll
        for (int i = 0; i < 8; i++)
#pragma unroll
            for (int j = 0; j < 8; j++) acc[i][j] = 0.f;

        for (int d0 = 0; d0 < DDIM; d0 += 32) {
            __syncthreads();   // previous compute done before overwrite
            // Es: 128k x 32d from emb (d contiguous) -> transposed store
#pragma unroll
            for (int i = 0; i < 4; i++) {
                int lin = tid + 256 * i;            // 0..1023 float4 slots
                int kl = lin >> 3;                  // 8 float4 per k row
                int dq = lin & 7;
                float4 v = *(const float4*)&emb[(size_t)(k0 + kl) * DDIM + d0 + dq * 4];
                Es[dq * 4 + 0][kl] = v.x;
                Es[dq * 4 + 1][kl] = v.y;
                Es[dq * 4 + 2][kl] = v.z;
                Es[dq * 4 + 3][kl] = v.w;
            }
            // Zs: 32d x 128n from g_ze (n contiguous) -> direct float4 store
#pragma unroll
            for (int i = 0; i < 4; i++) {
                int lin = tid + 256 * i;            // 0..1023 float4 slots
                int dd = lin >> 5;                  // 32 float4 per d row
                int nq = lin & 31;
                *(float4*)&Zs[dd][nq * 4] =
                    *(const float4*)&g_ze[((size_t)b * DDIM + d0 + dd) * NN + n0 + nq * 4];
            }
            if (d0 == 0 && tid < 128) esq_s[tid] = g_esq[k0 + tid];
            __syncthreads();
#pragma unroll
            for (int dc = 0; dc < 32; dc++) {
                float4 a0 = *(const float4*)&Es[dc][tk * 8];
                float4 a1 = *(const float4*)&Es[dc][tk * 8 + 4];
                float4 b0 = *(const float4*)&Zs[dc][tn * 8];
                float4 b1 = *(const float4*)&Zs[dc][tn * 8 + 4];
                float a[8] = {a0.x, a0.y, a0.z, a0.w, a1.x, a1.y, a1.z, a1.w};
                float bv[8] = {b0.x, b0.y, b0.z, b0.w, b1.x, b1.y, b1.z, b1.w};
#pragma unroll
                for (int i = 0; i < 8; i++)
#pragma unroll
                    for (int j = 0; j < 8; j++) acc[i][j] += a[i] * bv[j];
            }
        }
        // fused argmin update (k ascending => strict '<' keeps lowest index)
#pragma unroll
        for (int i = 0; i < 8; i++) {
            int k = k0 + tk * 8 + i;
            float eq = esq_s[tk * 8 + i];
#pragma unroll
            for (int j = 0; j < 8; j++) {
                float s = eq - 2.f * acc[i][j];
                if (s < vmin[j]) { vmin[j] = s; imin[j] = k; }
            }
        }
    }
    // cross-thread reduction over the 16 tk-slices per column (alias tile smem)
    float (*rv)[128] = (float(*)[128])&Es[0][0];
    int   (*ri)[128] = (int(*)[128])&Zs[0][0];
    __syncthreads();
#pragma unroll
    for (int j = 0; j < 8; j++) {
        rv[tk][tn * 8 + j] = vmin[j];
        ri[tk][tn * 8 + j] = imin[j];
    }
    __syncthreads();
    if (tid < 128) {
        int n = tid;
        float bv = rv[0][n];
        int bi = ri[0][n];
#pragma unroll
        for (int t = 1; t < 16; t++) {
            float v = rv[t][n];
            int i2 = ri[t][n];
            if (v < bv || (v == bv && i2 < bi)) { bv = v; bi = i2; }
        }
        g_minidx[(size_t)b * NN + n0 + n] = bi;
    }
}

// ============================================================
// zero scatter buffers (must re-zero every launch: graph replay)
// ============================================================
__global__ void zero_kernel() {
    int total = KKE * DDIM + KKE;
    for (int i = blockIdx.x * blockDim.x + threadIdx.x; i < total;
         i += gridDim.x * blockDim.x) {
        if (i < KKE * DDIM) g_zsum[i] = 0.f;
        else g_nsum[i - KKE * DDIM] = 0.f;
    }
}

// ============================================================
// gather zq -> out, scatter-add ze into z_sum / n_sum
// ============================================================
__global__ void gs_kernel(const float* __restrict__ emb, float* __restrict__ out)
{
    const int b = blockIdx.y;
    const int n = blockIdx.x * 32 + threadIdx.x;
    const int ty = threadIdx.y;
    const int idx = g_minidx[(size_t)b * NN + n];
#pragma unroll 4
    for (int d = ty; d < DDIM; d += 8) {
        size_t zoff = ((size_t)b * DDIM + d) * NN + n;
        float zev = g_ze[zoff];
        out[zoff] = emb[(size_t)idx * DDIM + d];   // straight-through value == zq
        atomicAdd(&g_zsum[(size_t)idx * DDIM + d], zev);
    }
    if (ty == 0) atomicAdd(&g_nsum[idx], 1.0f);
}

// ============================================================
// EMA finalize -> tail of d_out
// ============================================================
__global__ void ema_kernel(const float* __restrict__ ema_numer,
                           const float* __restrict__ ema_denom,
                           float* __restrict__ out)
{
    const size_t OUT_OFF = (size_t)BB * DDIM * NN;
    int i = blockIdx.x * blockDim.x + threadIdx.x;
    if (i < KKE * DDIM)
        out[OUT_OFF + i] = 0.99f * ema_numer[i] + 0.01f * g_zsum[i];
    if (i < KKE)
        out[OUT_OFF + (size_t)KKE * DDIM + i] = 0.99f * ema_denom[i] + 0.01f * g_nsum[i];
}

// ============================================================
extern "C" void kernel_launch(void* const* d_in, const int* in_sizes, int n_in,
                              void* d_out, int out_size)
{
    const float* z         = (const float*)d_in[0];
    const float* W         = (const float*)d_in[1];
    const float* emb       = (const float*)d_in[2];
    const float* ema_numer = (const float*)d_in[3];
    const float* ema_denom = (const float*)d_in[4];
    float* out = (float*)d_out;
    (void)in_sizes; (void)n_in; (void)out_size;

    // 1. codebook squared norms
    esq_kernel<<<(KKE * 32 + 255) / 256, 256>>>(emb);

    // 2. ze = W * z  (1x1 conv)
    {
        dim3 grid(NN / 128, DDIM / 64, BB);
        gemm1_kernel<<<grid, 256>>>(z, W);
    }

    // 3. fused distance GEMM + argmin
    {
        dim3 grid(NN / 128, BB);
        argmin_kernel<<<grid, 256>>>(emb);
    }

    // 4. zero scatter buffers
    zero_kernel<<<512, 256>>>();

    // 5. gather zq + scatter EMA statistics
    {
        dim3 grid(NN / 32, BB);
        dim3 blk(32, 8);
        gs_kernel<<<grid, blk>>>(emb, out);
    }

    // 6. EMA blend
    ema_kernel<<<(KKE * DDIM + 255) / 256, 256>>>(ema_numer, ema_denom, out);
}